// round 8
// baseline (speedup 1.0000x reference)
#include <cuda_runtime.h>
#include <cfloat>

// Problem constants (fixed by the dataset)
#define D        64
#define KCODES   1024
#define TM       128          // rows per CTA
#define TK       128          // codes per chunk
#define NCHUNK   (KCODES / TK)
#define NTILE    (TK / 8)     // 8-code n-tiles per chunk
#define THREADS  256
#define NROWS_MAX 131072

typedef unsigned int u32;

// Scratch (__device__ globals, allocation-free rule)
__device__ float g_en[KCODES];                        // ||e_k||^2, reference order
__device__ __align__(16) float g_ehi[KCODES * D];     // E hi, fragment-packed per chunk
__device__ __align__(16) float g_elo[KCODES * D];     // E lo
__device__ float g_partial[1024];
__device__ int   g_risky_count;
__device__ int   g_risky[NROWS_MAX];

// SMEM layout (bytes)
#define SM_EHI    0            // 32 KB (aliased by z staging before main loop)
#define SM_ELO    32768        // 32 KB
#define SM_IDX    65536        // 128 ints
#define SM_RED    66048        // 8 floats
#define SM_TOTAL  66176

__device__ __forceinline__ u32 to_tf32(float v) {
  u32 r; asm("cvt.rna.tf32.f32 %0, %1;" : "=r"(r) : "f"(v)); return r;
}

__device__ __forceinline__ void mma_tf32(float& d0, float& d1, float& d2, float& d3,
                                         u32 a0, u32 a1, u32 a2, u32 a3,
                                         u32 b0, u32 b1) {
  asm volatile(
    "mma.sync.aligned.m16n8k8.row.col.f32.tf32.tf32.f32 "
    "{%0,%1,%2,%3}, {%4,%5,%6,%7}, {%8,%9}, {%0,%1,%2,%3};"
    : "+f"(d0), "+f"(d1), "+f"(d2), "+f"(d3)
    : "r"(a0), "r"(a1), "r"(a2), "r"(a3), "r"(b0), "r"(b1));
}

// Reference-order squared-norm (verified): 4 lanes, (S0+S2)+(S1+S3)
__device__ __forceinline__ float ref_sqnorm_seq(const float* base) {
  float S[4] = {0.f, 0.f, 0.f, 0.f};
  #pragma unroll
  for (int i = 0; i < D / 4; i++)
    #pragma unroll
    for (int j = 0; j < 4; j++) {
      float v = base[4 * i + j];
      S[j] = __fadd_rn(S[j], __fmul_rn(v, v));
    }
  return __fadd_rn(__fadd_rn(S[0], S[2]), __fadd_rn(S[1], S[3]));
}

// ---------------------------------------------------------------------------
// Kernel 0a: codebook norms (verified)
// ---------------------------------------------------------------------------
__global__ void vq_en_kernel(const float* __restrict__ emb) {
  int k = blockIdx.x * blockDim.x + threadIdx.x;
  if (k < KCODES) g_en[k] = ref_sqnorm_seq(emb + (size_t)k * D);
}

// ---------------------------------------------------------------------------
// Kernel 0b: split E into tf32 hi/lo, packed in mma B-fragment order.
// Also resets the risky-row counter (every launch; graph-replay safe).
// ---------------------------------------------------------------------------
__global__ void vq_esplit_kernel(const float* __restrict__ emb) {
  int k = blockIdx.x * blockDim.x + threadIdx.x;
  if (k == 0) g_risky_count = 0;
  if (k >= KCODES) return;
  const int chunk = k >> 7, local = k & 127;
  const int tt = local >> 3, np = local & 7;
  const float* e = emb + (size_t)k * D;

  float ehi[D], elo[D];
  #pragma unroll
  for (int i = 0; i < D; i++) {
    float v = e[i];
    u32 hb = to_tf32(v);
    float hf = __uint_as_float(hb);
    ehi[i] = hf;
    elo[i] = __uint_as_float(to_tf32(v - hf));
  }
  #pragma unroll
  for (int ks = 0; ks < 8; ks++)
    #pragma unroll
    for (int kk = 0; kk < 4; kk++) {
      int l = np * 4 + kk;
      size_t off = (size_t)chunk * 8192 + (size_t)((tt * 8 + ks) * 32 + l) * 2;
      *(float2*)(g_ehi + off) = make_float2(ehi[8 * ks + kk], ehi[8 * ks + kk + 4]);
      *(float2*)(g_elo + off) = make_float2(elo[8 * ks + kk], elo[8 * ks + kk + 4]);
    }
}

// ---------------------------------------------------------------------------
// Kernel 1: tf32x3 mma.sync scores + quantized argmin + top-2 risky flagging
// ---------------------------------------------------------------------------
__global__ void __launch_bounds__(THREADS, 2)
vq_main_kernel(const float* __restrict__ z, const float* __restrict__ emb,
               float* __restrict__ out_zq, float* __restrict__ out_idx) {
  extern __shared__ __align__(16) char smem[];
  float2* e_hi  = (float2*)(smem + SM_EHI);
  float2* e_lo  = (float2*)(smem + SM_ELO);
  int*    sidx  = (int*)(smem + SM_IDX);
  float*  sred  = (float*)(smem + SM_RED);
  float*  zstage = (float*)(smem + SM_EHI);   // alias: consumed before E loads

  const int t = threadIdx.x;
  const int w = t >> 5, lane = t & 31;
  const int g = lane >> 2, m = lane & 3;
  const int lr0 = w * 16 + g, lr1 = lr0 + 8;  // this thread's two rows (local)
  const size_t rowBase = (size_t)blockIdx.x * TM;

  // --- stage z tile (raw row-major [128][64]) ---
  {
    const float4* src = (const float4*)(z + rowBase * D);
    float4* dst = (float4*)zstage;
    #pragma unroll
    for (int i = 0; i < 8; i++) dst[t + i * THREADS] = src[t + i * THREADS];
  }
  __syncthreads();

  // --- A fragments (persistent) + reference-order zn via quad shfl ---
  u32 ah0[8], ah1[8], ah2[8], ah3[8];
  u32 al0[8], al1[8], al2[8], al3[8];
  float zn0, zn1;
  {
    const float* zr0 = zstage + lr0 * D;
    const float* zr1 = zstage + lr1 * D;
    float S0 = 0.f, S1 = 0.f;          // S_m partial for rows r0, r1
    #pragma unroll
    for (int ks = 0; ks < 8; ks++) {
      float v00 = zr0[8 * ks + m], v01 = zr0[8 * ks + m + 4];
      float v10 = zr1[8 * ks + m], v11 = zr1[8 * ks + m + 4];
      S0 = __fadd_rn(S0, __fmul_rn(v00, v00));
      S0 = __fadd_rn(S0, __fmul_rn(v01, v01));
      S1 = __fadd_rn(S1, __fmul_rn(v10, v10));
      S1 = __fadd_rn(S1, __fmul_rn(v11, v11));
      ah0[ks] = to_tf32(v00); ah2[ks] = to_tf32(v01);
      ah1[ks] = to_tf32(v10); ah3[ks] = to_tf32(v11);
      al0[ks] = to_tf32(v00 - __uint_as_float(ah0[ks]));
      al2[ks] = to_tf32(v01 - __uint_as_float(ah2[ks]));
      al1[ks] = to_tf32(v10 - __uint_as_float(ah1[ks]));
      al3[ks] = to_tf32(v11 - __uint_as_float(ah3[ks]));
    }
    // zn = (S0+S2)+(S1+S3): quad butterfly, commutative fadd keeps bits equal
    float T0 = __fadd_rn(S0, __shfl_xor_sync(0xFFFFFFFFu, S0, 2));
    zn0 = __fadd_rn(T0, __shfl_xor_sync(0xFFFFFFFFu, T0, 1));
    float T1 = __fadd_rn(S1, __shfl_xor_sync(0xFFFFFFFFu, S1, 2));
    zn1 = __fadd_rn(T1, __shfl_xor_sync(0xFFFFFFFFu, T1, 1));
  }
  __syncthreads();   // z staging fully consumed; smem now free for E

  float min0v = FLT_MAX, min1v = FLT_MAX;   // best quantized d
  float min0s = FLT_MAX, min1s = FLT_MAX;   // second-best (value only)
  int   min0i = 0,       min1i = 0;

  for (int ch = 0; ch < NCHUNK; ch++) {
    // load E chunk (pre-packed fragment images): 2 x 32 KB
    {
      const float4* sh = (const float4*)(g_ehi + (size_t)ch * 8192);
      const float4* sl = (const float4*)(g_elo + (size_t)ch * 8192);
      float4* dh = (float4*)e_hi;
      float4* dl = (float4*)e_lo;
      #pragma unroll
      for (int i = 0; i < 8; i++) {
        dh[t + i * THREADS] = sh[t + i * THREADS];
        dl[t + i * THREADS] = sl[t + i * THREADS];
      }
    }
    __syncthreads();

    #pragma unroll
    for (int tt = 0; tt < NTILE; tt++) {
      // B-hi fragments for this tile (kept in regs; reused by pass 3)
      u32 bh0[8], bh1[8];
      #pragma unroll
      for (int ks = 0; ks < 8; ks++) {
        float2 b = e_hi[(tt * 8 + ks) * 32 + lane];
        bh0[ks] = __float_as_uint(b.x);
        bh1[ks] = __float_as_uint(b.y);
      }
      // pass 1: zh . eh  -> main accumulator
      float d0 = 0.f, d1 = 0.f, d2 = 0.f, d3 = 0.f;
      #pragma unroll
      for (int ks = 0; ks < 8; ks++)
        mma_tf32(d0, d1, d2, d3, ah0[ks], ah1[ks], ah2[ks], ah3[ks], bh0[ks], bh1[ks]);
      // pass 2+3: zh . el + zl . eh -> small cross accumulator
      float x0 = 0.f, x1 = 0.f, x2 = 0.f, x3 = 0.f;
      #pragma unroll
      for (int ks = 0; ks < 8; ks++) {
        float2 b = e_lo[(tt * 8 + ks) * 32 + lane];
        mma_tf32(x0, x1, x2, x3, ah0[ks], ah1[ks], ah2[ks], ah3[ks],
                 __float_as_uint(b.x), __float_as_uint(b.y));
      }
      #pragma unroll
      for (int ks = 0; ks < 8; ks++)
        mma_tf32(x0, x1, x2, x3, al0[ks], al1[ks], al2[ks], al3[ks], bh0[ks], bh1[ks]);

      // epilogue: d-regs map to rows (g,g+8) x cols (2m, 2m+1) of this tile
      const int cb = ch * TK + tt * 8 + 2 * m;
      float2 en2 = __ldg((const float2*)(g_en + cb));
      float dot, dv;
      dot = __fadd_rn(d0, x0);
      dv  = __fsub_rn(__fadd_rn(zn0, en2.x), __fadd_rn(dot, dot));
      if (dv < min0v) { min0s = min0v; min0v = dv; min0i = cb; }
      else if (dv < min0s) min0s = dv;
      dot = __fadd_rn(d1, x1);
      dv  = __fsub_rn(__fadd_rn(zn0, en2.y), __fadd_rn(dot, dot));
      if (dv < min0v) { min0s = min0v; min0v = dv; min0i = cb + 1; }
      else if (dv < min0s) min0s = dv;
      dot = __fadd_rn(d2, x2);
      dv  = __fsub_rn(__fadd_rn(zn1, en2.x), __fadd_rn(dot, dot));
      if (dv < min1v) { min1s = min1v; min1v = dv; min1i = cb; }
      else if (dv < min1s) min1s = dv;
      dot = __fadd_rn(d3, x3);
      dv  = __fsub_rn(__fadd_rn(zn1, en2.y), __fadd_rn(dot, dot));
      if (dv < min1v) { min1s = min1v; min1v = dv; min1i = cb + 1; }
      else if (dv < min1s) min1s = dv;
    }
    __syncthreads();   // all tiles consumed before next chunk overwrites E
  }

  // --- cross-lane top-2 argmin within each quad (tie -> lowest index) ---
  #pragma unroll
  for (int off = 1; off <= 2; off <<= 1) {
    float ov = __shfl_xor_sync(0xFFFFFFFFu, min0v, off);
    int   oi = __shfl_xor_sync(0xFFFFFFFFu, min0i, off);
    float os = __shfl_xor_sync(0xFFFFFFFFu, min0s, off);
    if (ov < min0v || (ov == min0v && oi < min0i)) {
      min0s = fminf(min0v, os); min0v = ov; min0i = oi;
    } else min0s = fminf(min0s, ov);
    ov = __shfl_xor_sync(0xFFFFFFFFu, min1v, off);
    oi = __shfl_xor_sync(0xFFFFFFFFu, min1i, off);
    os = __shfl_xor_sync(0xFFFFFFFFu, min1s, off);
    if (ov < min1v || (ov == min1v && oi < min1i)) {
      min1s = fminf(min1v, os); min1v = ov; min1i = oi;
    } else min1s = fminf(min1s, ov);
  }

  float contrib = 0.f;
  if (m == 0) {
    sidx[lr0] = min0i; sidx[lr1] = min1i;
    out_idx[rowBase + lr0] = (float)min0i;
    out_idx[rowBase + lr1] = (float)min1i;
    contrib = min0v + min1v;   // quantized d_min values (verified semantics)
    // risky rows: top-2 gap within 8 grid steps -> exact rescore later
    if (min0s - min0v <= min0v * 1e-6f) {
      int p = atomicAdd(&g_risky_count, 1);
      g_risky[p] = (int)(rowBase + lr0);
    }
    if (min1s - min1v <= min1v * 1e-6f) {
      int p = atomicAdd(&g_risky_count, 1);
      g_risky[p] = (int)(rowBase + lr1);
    }
  }
  // warp sum of loss contributions
  #pragma unroll
  for (int o = 16; o > 0; o >>= 1) contrib += __shfl_xor_sync(0xFFFFFFFFu, contrib, o);
  if (lane == 0) sred[w] = contrib;
  __syncthreads();
  if (t == 0) {
    float tot = 0.f;
    #pragma unroll
    for (int i = 0; i < 8; i++) tot += sred[i];
    g_partial[blockIdx.x] = tot;
  }

  // coalesced z_q gather: 16 float4 lanes per row
  for (int j = t; j < TM * (D / 4); j += THREADS) {
    int r2 = j >> 4, p = j & 15;
    ((float4*)(out_zq + (rowBase + r2) * D))[p] =
        ((const float4*)(emb + (size_t)sidx[r2] * D))[p];
  }
}

// ---------------------------------------------------------------------------
// Kernel 1b: exact rescore of risky rows (verified SIMT numerics).
// One warp per row; all 1024 codes; overwrites idx + z_q.
// ---------------------------------------------------------------------------
__global__ void __launch_bounds__(256, 4)
vq_fix_kernel(const float* __restrict__ z, const float* __restrict__ emb,
              float* __restrict__ out_zq, float* __restrict__ out_idx) {
  __shared__ float zrow[8][D];
  const int wl = threadIdx.x >> 5, lane = threadIdx.x & 31;
  const int wg = blockIdx.x * 8 + wl;
  const int nw = gridDim.x * 8;
  const int cnt = g_risky_count;

  for (int i = wg; i < cnt; i += nw) {
    const int row = g_risky[i];
    ((float2*)zrow[wl])[lane] = ((const float2*)(z + (size_t)row * D))[lane];
    __syncwarp();
    // zn in reference order
    float S[4] = {0.f, 0.f, 0.f, 0.f};
    #pragma unroll
    for (int ii = 0; ii < D / 4; ii++)
      #pragma unroll
      for (int j = 0; j < 4; j++) {
        float v = zrow[wl][4 * ii + j];
        S[j] = __fadd_rn(S[j], __fmul_rn(v, v));
      }
    float zn = __fadd_rn(__fadd_rn(S[0], S[2]), __fadd_rn(S[1], S[3]));

    float bestv = FLT_MAX; int besti = 0;
    for (int j = 0; j < KCODES / 32; j++) {
      const int code = j * 32 + lane;
      const float* e = emb + (size_t)code * D;
      float acc = 0.f;
      #pragma unroll
      for (int dd = 0; dd < D; dd++)
        acc = __fmaf_rn(zrow[wl][dd], __ldg(e + dd), acc);
      float dv = __fsub_rn(__fadd_rn(zn, __ldg(&g_en[code])), __fadd_rn(acc, acc));
      if (dv < bestv) { bestv = dv; besti = code; }
    }
    #pragma unroll
    for (int off = 16; off > 0; off >>= 1) {
      float ov = __shfl_xor_sync(0xFFFFFFFFu, bestv, off);
      int   oi = __shfl_xor_sync(0xFFFFFFFFu, besti, off);
      if (ov < bestv || (ov == bestv && oi < besti)) { bestv = ov; besti = oi; }
    }
    if (lane == 0) out_idx[row] = (float)besti;
    if (lane < 16)
      ((float4*)(out_zq + (size_t)row * D))[lane] =
          ((const float4*)(emb + (size_t)besti * D))[lane];
    __syncwarp();
  }
}

// ---------------------------------------------------------------------------
// Kernel 2: deterministic loss reduction (double accumulation)
// loss = 1.25 * sum(d_min) / (N*D)
// ---------------------------------------------------------------------------
__global__ void vq_finish_kernel(float* __restrict__ out_loss, int nb, long long nd) {
  int t = threadIdx.x;
  double v = (t < nb) ? (double)g_partial[t] : 0.0;
  #pragma unroll
  for (int o = 16; o > 0; o >>= 1) v += __shfl_xor_sync(0xFFFFFFFFu, v, o);
  __shared__ double red[32];
  if ((t & 31) == 0) red[t >> 5] = v;
  __syncthreads();
  if (t < 32) {
    double w = (t < (int)(blockDim.x >> 5)) ? red[t] : 0.0;
    #pragma unroll
    for (int o = 16; o > 0; o >>= 1) w += __shfl_xor_sync(0xFFFFFFFFu, w, o);
    if (t == 0) out_loss[0] = (float)(1.25 * w / (double)nd);
  }
}

// ---------------------------------------------------------------------------
extern "C" void kernel_launch(void* const* d_in, const int* in_sizes, int n_in,
                              void* d_out, int out_size) {
  const float* z   = (const float*)d_in[0];   // [N,1,64] fp32
  const float* emb = (const float*)d_in[1];   // [1024,64] fp32
  float* out = (float*)d_out;

  const int N = in_sizes[0] / D;              // 131072
  float* out_zq   = out;                      // [N*D]
  float* out_idx  = out + (size_t)N * D;      // [N] (indices as float)
  float* out_loss = out_idx + N;              // [1]

  vq_en_kernel<<<(KCODES + 255) / 256, 256>>>(emb);
  vq_esplit_kernel<<<(KCODES + 127) / 128, 128>>>(emb);

  cudaFuncSetAttribute(vq_main_kernel,
                       cudaFuncAttributeMaxDynamicSharedMemorySize, SM_TOTAL);
  vq_main_kernel<<<N / TM, THREADS, SM_TOTAL>>>(z, emb, out_zq, out_idx);

  vq_fix_kernel<<<128, 256>>>(z, emb, out_zq, out_idx);

  vq_finish_kernel<<<1, 1024>>>(out_loss, N / TM, (long long)N * D);
}